// round 12
// baseline (speedup 1.0000x reference)
#include <cuda_runtime.h>
#include <cuda_bf16.h>
#include <math.h>
#include <stdint.h>

#define N_TOK 4096
#define DIM   768
#define NH    12
#define HD    64
#define SCALE 0.125f   // 1/sqrt(64)
#define LOG2E 1.44269504088896340736f
#define NSPLIT 4
#define TILES_PER_SPLIT (N_TOK / 64 / NSPLIT)   // 16

// Scratch (allocation-free rule: device globals)
// g_q holds tf32 bits of q*SCALE*LOG2E; g_k/g_v hold tf32 bits of k/v.
__device__ float g_q[NH * N_TOK * HD];
__device__ float g_k[NH * N_TOK * HD];
__device__ float g_v[NH * N_TOK * HD];
__device__ float g_att[N_TOK * DIM];
__device__ float g_po[NSPLIT * N_TOK * DIM];        // partial O per split
__device__ float g_pl[NSPLIT * NH * N_TOK];         // partial row sums

// ---------------------------------------------------------------------------
// helpers
// ---------------------------------------------------------------------------
__device__ __forceinline__ uint32_t f2tf(float f) {
    uint32_t r;
    asm("cvt.rna.tf32.f32 %0, %1;" : "=r"(r) : "f"(f));
    return r;
}

__device__ __forceinline__ float ex2(float x) {
    float r;
    asm("ex2.approx.f32 %0, %1;" : "=f"(r) : "f"(x));
    return r;
}

__device__ __forceinline__ void mma_tf32(float& c0, float& c1, float& c2, float& c3,
                                         uint32_t a0, uint32_t a1, uint32_t a2, uint32_t a3,
                                         uint32_t b0, uint32_t b1) {
    asm volatile("mma.sync.aligned.m16n8k8.row.col.f32.tf32.tf32.f32 "
                 "{%0,%1,%2,%3}, {%4,%5,%6,%7}, {%8,%9}, {%0,%1,%2,%3};"
                 : "+f"(c0), "+f"(c1), "+f"(c2), "+f"(c3)
                 : "r"(a0), "r"(a1), "r"(a2), "r"(a3), "r"(b0), "r"(b1));
}

__device__ __forceinline__ uint32_t cvta_smem(const void* p) {
    uint32_t a;
    asm("{ .reg .u64 t; cvta.to.shared.u64 t, %1; cvt.u32.u64 %0, t; }"
        : "=r"(a) : "l"(p));
    return a;
}

#define CP_ASYNC16(dst, src) \
    asm volatile("cp.async.cg.shared.global [%0], [%1], 16;" :: "r"(dst), "l"(src))
#define CP_COMMIT() asm volatile("cp.async.commit_group;" ::: "memory")
#define CP_WAIT0()  asm volatile("cp.async.wait_group 0;" ::: "memory")

// Write tf32 bits at scatter time. Q additionally pre-scaled by SCALE*LOG2E so
// flash's softmax is a bare ex2.approx. Numerically: p = 2^(s*log2e) = exp(s).
__device__ __forceinline__ void qkv_scatter(int m, int c, float v) {
    int s = c / DIM;
    int rem = c - s * DIM;
    int h = rem >> 6;
    int d = rem & 63;
    float* dst = (s == 0) ? g_q : (s == 1) ? g_k : g_v;
    float val = (s == 0) ? v * (SCALE * LOG2E) : v;
    dst[((size_t)h * N_TOK + m) * HD + d] = __uint_as_float(f2tf(val));
}

// ---------------------------------------------------------------------------
// Kernel 1: qkv = x @ w_qkv^T  (tf32 mma.sync), scatter into head-major Q/K/V
// v2: 128 threads (4 warps), warp grid 2x2, warp tile 64x64 (4x8 mma tiles).
// Halves smem fragment traffic per HMMA vs the 8-warp 64x32 version.
// ---------------------------------------------------------------------------
__global__ __launch_bounds__(128) void qkv_mma_kernel(const float* __restrict__ A,
                                                      const float* __restrict__ W) {
    __shared__ uint32_t sA[128 * 36];
    __shared__ uint32_t sB[128 * 36];
    const int bm = blockIdx.y * 128;
    const int bn = blockIdx.x * 128;
    const int tid = threadIdx.x;
    const int wid = tid >> 5;      // 0..3
    const int lane = tid & 31;
    const int gid = lane >> 2;
    const int tig = lane & 3;
    const int wm = wid >> 1;       // 0..1
    const int wn = wid & 1;        // 0..1

    float acc[4][8][4];
#pragma unroll
    for (int mi = 0; mi < 4; mi++)
#pragma unroll
        for (int ni = 0; ni < 8; ni++)
#pragma unroll
            for (int t = 0; t < 4; t++) acc[mi][ni][t] = 0.f;

    const int lr = tid >> 3;          // 0..15
    const int lc = (tid & 7) << 2;    // 0..28

    for (int k0 = 0; k0 < DIM; k0 += 32) {
        float4 av[8], bv[8];
#pragma unroll
        for (int i = 0; i < 8; i++) {
            int r = lr + i * 16;
            av[i] = *(const float4*)(A + (size_t)(bm + r) * DIM + k0 + lc);
            bv[i] = *(const float4*)(W + (size_t)(bn + r) * DIM + k0 + lc);
        }
        __syncthreads();
#pragma unroll
        for (int i = 0; i < 8; i++) {
            int r = lr + i * 16;
            *(uint4*)(sA + r * 36 + lc) =
                make_uint4(f2tf(av[i].x), f2tf(av[i].y), f2tf(av[i].z), f2tf(av[i].w));
            *(uint4*)(sB + r * 36 + lc) =
                make_uint4(f2tf(bv[i].x), f2tf(bv[i].y), f2tf(bv[i].z), f2tf(bv[i].w));
        }
        __syncthreads();

#pragma unroll
        for (int ks = 0; ks < 4; ks++) {
            const int kk = ks * 8;
            uint32_t af[4][4];
#pragma unroll
            for (int mi = 0; mi < 4; mi++) {
                int row = wm * 64 + mi * 16 + gid;
                af[mi][0] = sA[row * 36 + kk + tig];
                af[mi][1] = sA[(row + 8) * 36 + kk + tig];
                af[mi][2] = sA[row * 36 + kk + tig + 4];
                af[mi][3] = sA[(row + 8) * 36 + kk + tig + 4];
            }
            uint32_t bf[8][2];
#pragma unroll
            for (int ni = 0; ni < 8; ni++) {
                int n = wn * 64 + ni * 8 + gid;
                bf[ni][0] = sB[n * 36 + kk + tig];
                bf[ni][1] = sB[n * 36 + kk + tig + 4];
            }
#pragma unroll
            for (int mi = 0; mi < 4; mi++)
#pragma unroll
                for (int ni = 0; ni < 8; ni++)
                    mma_tf32(acc[mi][ni][0], acc[mi][ni][1], acc[mi][ni][2], acc[mi][ni][3],
                             af[mi][0], af[mi][1], af[mi][2], af[mi][3],
                             bf[ni][0], bf[ni][1]);
        }
    }

#pragma unroll
    for (int mi = 0; mi < 4; mi++) {
        int r = bm + wm * 64 + mi * 16 + gid;
#pragma unroll
        for (int ni = 0; ni < 8; ni++) {
            int c = bn + wn * 64 + ni * 8 + 2 * tig;
            qkv_scatter(r, c, acc[mi][ni][0]);
            qkv_scatter(r, c + 1, acc[mi][ni][1]);
            qkv_scatter(r + 8, c, acc[mi][ni][2]);
            qkv_scatter(r + 8, c + 1, acc[mi][ni][3]);
        }
    }
}

// ---------------------------------------------------------------------------
// Kernel 2: flash attention, tf32 mma.sync, 4-way split-K, cp.async pipeline.
// grid (4096/128, 12, NSPLIT), 256 threads (8 warps), 2 CTAs/SM.
// K/V already tf32 bits in gmem -> raw 16B cp.async into double-buffered smem.
// Softmax: p = ex2(s) with log2(e) folded into Q. Partials additive.
// smem words: sK[2][64*68] | sV[2][64*72] | sP[128*68]
// ---------------------------------------------------------------------------
#define SKS 68
#define SVS 72
#define SPS 68
#define KOFF(b) ((b) * (64 * SKS))
#define VOFF(b) (2 * 64 * SKS + (b) * (64 * SVS))
#define POFF    (2 * 64 * SKS + 2 * 64 * SVS)
#define FLASH_SMEM ((2 * 64 * SKS + 2 * 64 * SVS + 128 * SPS) * 4)

__global__ __launch_bounds__(256, 2) void flash_split_kernel() {
    extern __shared__ uint32_t smem[];
    uint32_t* sP = smem + POFF;
    const uint32_t sbase = cvta_smem(smem);

    const int tid = threadIdx.x;
    const int wid = tid >> 5;
    const int lane = tid & 31;
    const int gid = lane >> 2;
    const int tig = lane & 3;
    const int h = blockIdx.y;
    const int q0 = blockIdx.x * 128;
    const int sp = blockIdx.z;

    const float* Qh = g_q + (size_t)h * N_TOK * HD;
    const float* Kh = g_k + (size_t)h * N_TOK * HD;
    const float* Vh = g_v + (size_t)h * N_TOK * HD;

    // Q fragments: already tf32 bits (pre-scaled) in gmem
    const int qrow = q0 + wid * 16 + gid;
    uint32_t qa[8][4];
#pragma unroll
    for (int kt = 0; kt < 8; kt++) {
        int c = kt * 8 + tig;
        qa[kt][0] = __float_as_uint(Qh[(size_t)qrow * HD + c]);
        qa[kt][1] = __float_as_uint(Qh[(size_t)(qrow + 8) * HD + c]);
        qa[kt][2] = __float_as_uint(Qh[(size_t)qrow * HD + c + 4]);
        qa[kt][3] = __float_as_uint(Qh[(size_t)(qrow + 8) * HD + c + 4]);
    }

    float o[8][4];
#pragma unroll
    for (int nt = 0; nt < 8; nt++)
#pragma unroll
        for (int t = 0; t < 4; t++) o[nt][t] = 0.f;
    float l0 = 0.f, l1 = 0.f;

    const int ldr = tid >> 4;          // 0..15
    const int ldc = (tid & 15) << 2;   // word col 0..60
    const int prow = wid * 16 + gid;

    const int kb_beg = sp * (TILES_PER_SPLIT * 64);

    // prologue: async-copy tile 0 into buffer 0
#pragma unroll
    for (int i = 0; i < 4; i++) {
        int r = ldr + i * 16;
        CP_ASYNC16(sbase + (KOFF(0) + r * SKS + ldc) * 4,
                   Kh + (size_t)(kb_beg + r) * HD + ldc);
        CP_ASYNC16(sbase + (VOFF(0) + r * SVS + ldc) * 4,
                   Vh + (size_t)(kb_beg + r) * HD + ldc);
    }
    CP_COMMIT();

    for (int it = 0; it < TILES_PER_SPLIT; it++) {
        const int b = it & 1;
        const uint32_t* sK = smem + KOFF(b);
        const uint32_t* sV = smem + VOFF(b);

        CP_WAIT0();          // tile it landed (had full previous compute to fly)
        __syncthreads();     // visibility + everyone done reading buf b from it-2

        // issue copies for tile it+1 into the other buffer; overlaps compute
        if (it + 1 < TILES_PER_SPLIT) {
            const int kbn = kb_beg + (it + 1) * 64;
            const int nb = (it + 1) & 1;
#pragma unroll
            for (int i = 0; i < 4; i++) {
                int r = ldr + i * 16;
                CP_ASYNC16(sbase + (KOFF(nb) + r * SKS + ldc) * 4,
                           Kh + (size_t)(kbn + r) * HD + ldc);
                CP_ASYNC16(sbase + (VOFF(nb) + r * SVS + ldc) * 4,
                           Vh + (size_t)(kbn + r) * HD + ldc);
            }
            CP_COMMIT();
        }

        // S = Q K^T : per warp 16 x 64
        float s[8][4];
#pragma unroll
        for (int nt = 0; nt < 8; nt++)
#pragma unroll
            for (int t = 0; t < 4; t++) s[nt][t] = 0.f;
#pragma unroll
        for (int kt = 0; kt < 8; kt++) {
#pragma unroll
            for (int nt = 0; nt < 8; nt++) {
                uint32_t b0 = sK[(nt * 8 + gid) * SKS + kt * 8 + tig];
                uint32_t b1 = sK[(nt * 8 + gid) * SKS + kt * 8 + tig + 4];
                mma_tf32(s[nt][0], s[nt][1], s[nt][2], s[nt][3],
                         qa[kt][0], qa[kt][1], qa[kt][2], qa[kt][3], b0, b1);
            }
        }

        // softmax: p = 2^s (log2e folded into Q), write P to smem
#pragma unroll
        for (int nt = 0; nt < 8; nt++) {
            float p0 = ex2(s[nt][0]);
            float p1 = ex2(s[nt][1]);
            float p2 = ex2(s[nt][2]);
            float p3 = ex2(s[nt][3]);
            l0 += p0 + p1;
            l1 += p2 + p3;
            int c = nt * 8 + 2 * tig;
            sP[prow * SPS + c] = f2tf(p0);
            sP[prow * SPS + c + 1] = f2tf(p1);
            sP[(prow + 8) * SPS + c] = f2tf(p2);
            sP[(prow + 8) * SPS + c + 1] = f2tf(p3);
        }
        __syncwarp();   // sP rows of this q-group are warp-local

        // O += P V
#pragma unroll
        for (int kt = 0; kt < 8; kt++) {
            uint32_t pa0 = sP[prow * SPS + kt * 8 + tig];
            uint32_t pa1 = sP[(prow + 8) * SPS + kt * 8 + tig];
            uint32_t pa2 = sP[prow * SPS + kt * 8 + tig + 4];
            uint32_t pa3 = sP[(prow + 8) * SPS + kt * 8 + tig + 4];
#pragma unroll
            for (int nt = 0; nt < 8; nt++) {
                uint32_t b0 = sV[(kt * 8 + tig) * SVS + nt * 8 + gid];
                uint32_t b1 = sV[(kt * 8 + tig + 4) * SVS + nt * 8 + gid];
                mma_tf32(o[nt][0], o[nt][1], o[nt][2], o[nt][3],
                         pa0, pa1, pa2, pa3, b0, b1);
            }
        }
    }

    // quad-reduce row sums
    l0 += __shfl_xor_sync(0xffffffffu, l0, 1);
    l0 += __shfl_xor_sync(0xffffffffu, l0, 2);
    l1 += __shfl_xor_sync(0xffffffffu, l1, 1);
    l1 += __shfl_xor_sync(0xffffffffu, l1, 2);

    // write unnormalized partials
    float* po = g_po + (size_t)sp * N_TOK * DIM;
#pragma unroll
    for (int nt = 0; nt < 8; nt++) {
        int c = h * HD + nt * 8 + 2 * tig;
        *(float2*)(po + (size_t)(q0 + prow) * DIM + c) = make_float2(o[nt][0], o[nt][1]);
        *(float2*)(po + (size_t)(q0 + prow + 8) * DIM + c) = make_float2(o[nt][2], o[nt][3]);
    }
    if (tig == 0) {
        g_pl[((size_t)sp * NH + h) * N_TOK + q0 + prow] = l0;
        g_pl[((size_t)sp * NH + h) * N_TOK + q0 + prow + 8] = l1;
    }
}

// ---------------------------------------------------------------------------
// Kernel 2b: combine split partials: g_att = sum(O_s) / sum(l_s)
// ---------------------------------------------------------------------------
__global__ __launch_bounds__(256) void combine_kernel() {
    const int idx = blockIdx.x * 256 + threadIdx.x;   // float4 index
    const int n = idx / (DIM / 4);
    const int c4 = idx - n * (DIM / 4);
    const int h = c4 >> 4;                            // (c4*4)/64

    float l = 0.f;
    float4 acc = make_float4(0.f, 0.f, 0.f, 0.f);
#pragma unroll
    for (int sp = 0; sp < NSPLIT; sp++) {
        l += g_pl[((size_t)sp * NH + h) * N_TOK + n];
        float4 v = *(const float4*)(g_po + (size_t)sp * N_TOK * DIM + (size_t)n * DIM + c4 * 4);
        acc.x += v.x; acc.y += v.y; acc.z += v.z; acc.w += v.w;
    }
    float inv = 1.f / l;
    *(float4*)(g_att + (size_t)n * DIM + c4 * 4) =
        make_float4(acc.x * inv, acc.y * inv, acc.z * inv, acc.w * inv);
}

// ---------------------------------------------------------------------------
// Kernel 3: out = att @ w_proj^T + b_proj  (tf32 mma.sync)
// BM=64, BN=128 -> grid (6, 64) = 384 CTAs, 3 CTAs/SM: single ~86% wave.
// ---------------------------------------------------------------------------
__global__ __launch_bounds__(256, 3) void proj_mma_kernel(const float* __restrict__ W,
                                                          const float* __restrict__ bias,
                                                          float* __restrict__ out) {
    __shared__ uint32_t sA[64 * 36];
    __shared__ uint32_t sB[128 * 36];
    const int bm = blockIdx.y * 64;
    const int bn = blockIdx.x * 128;
    const int tid = threadIdx.x;
    const int wid = tid >> 5;
    const int lane = tid & 31;
    const int gid = lane >> 2;
    const int tig = lane & 3;
    const int wm = wid >> 2;   // 0..1 (32 rows each)
    const int wn = wid & 3;    // 0..3 (32 cols each)
    const float* A = g_att;

    float acc[2][4][4];
#pragma unroll
    for (int mi = 0; mi < 2; mi++)
#pragma unroll
        for (int ni = 0; ni < 4; ni++)
#pragma unroll
            for (int t = 0; t < 4; t++) acc[mi][ni][t] = 0.f;

    const int lr = tid >> 3;          // 0..31
    const int lc = (tid & 7) << 2;    // 0..28

    for (int k0 = 0; k0 < DIM; k0 += 32) {
        float4 av[2], bv[4];
#pragma unroll
        for (int i = 0; i < 2; i++)
            av[i] = *(const float4*)(A + (size_t)(bm + lr + i * 32) * DIM + k0 + lc);
#pragma unroll
        for (int i = 0; i < 4; i++)
            bv[i] = *(const float4*)(W + (size_t)(bn + lr + i * 32) * DIM + k0 + lc);
        __syncthreads();
#pragma unroll
        for (int i = 0; i < 2; i++) {
            int r = lr + i * 32;
            *(uint4*)(sA + r * 36 + lc) =
                make_uint4(f2tf(av[i].x), f2tf(av[i].y), f2tf(av[i].z), f2tf(av[i].w));
        }
#pragma unroll
        for (int i = 0; i < 4; i++) {
            int r = lr + i * 32;
            *(uint4*)(sB + r * 36 + lc) =
                make_uint4(f2tf(bv[i].x), f2tf(bv[i].y), f2tf(bv[i].z), f2tf(bv[i].w));
        }
        __syncthreads();

#pragma unroll
        for (int ks = 0; ks < 4; ks++) {
            const int kk = ks * 8;
            uint32_t af[2][4];
#pragma unroll
            for (int mi = 0; mi < 2; mi++) {
                int row = wm * 32 + mi * 16 + gid;
                af[mi][0] = sA[row * 36 + kk + tig];
                af[mi][1] = sA[(row + 8) * 36 + kk + tig];
                af[mi][2] = sA[row * 36 + kk + tig + 4];
                af[mi][3] = sA[(row + 8) * 36 + kk + tig + 4];
            }
            uint32_t bf[4][2];
#pragma unroll
            for (int ni = 0; ni < 4; ni++) {
                int n = wn * 32 + ni * 8 + gid;
                bf[ni][0] = sB[n * 36 + kk + tig];
                bf[ni][1] = sB[n * 36 + kk + tig + 4];
            }
#pragma unroll
            for (int mi = 0; mi < 2; mi++)
#pragma unroll
                for (int ni = 0; ni < 4; ni++)
                    mma_tf32(acc[mi][ni][0], acc[mi][ni][1], acc[mi][ni][2], acc[mi][ni][3],
                             af[mi][0], af[mi][1], af[mi][2], af[mi][3],
                             bf[ni][0], bf[ni][1]);
        }
    }

#pragma unroll
    for (int mi = 0; mi < 2; mi++) {
        int r = bm + wm * 32 + mi * 16 + gid;
#pragma unroll
        for (int ni = 0; ni < 4; ni++) {
            int c = bn + wn * 32 + ni * 8 + 2 * tig;
            out[(size_t)r * DIM + c]           = acc[mi][ni][0] + bias[c];
            out[(size_t)r * DIM + c + 1]       = acc[mi][ni][1] + bias[c + 1];
            out[(size_t)(r + 8) * DIM + c]     = acc[mi][ni][2] + bias[c];
            out[(size_t)(r + 8) * DIM + c + 1] = acc[mi][ni][3] + bias[c + 1];
        }
    }
}

// ---------------------------------------------------------------------------
extern "C" void kernel_launch(void* const* d_in, const int* in_sizes, int n_in,
                              void* d_out, int out_size) {
    const float* x      = (const float*)d_in[0];   // [4096, 768]
    const float* w_qkv  = (const float*)d_in[1];   // [2304, 768]
    const float* w_proj = (const float*)d_in[2];   // [768, 768]
    const float* b_proj = (const float*)d_in[3];   // [768]
    float* out = (float*)d_out;                    // [4096, 768]

    static bool attr_set = false;
    if (!attr_set) {
        cudaFuncSetAttribute(flash_split_kernel,
                             cudaFuncAttributeMaxDynamicSharedMemorySize, FLASH_SMEM);
        attr_set = true;
    }

    {
        dim3 grid(2304 / 128, N_TOK / 128);
        qkv_mma_kernel<<<grid, 128>>>(x, w_qkv);
    }
    {
        dim3 grid(N_TOK / 128, NH, NSPLIT);
        flash_split_kernel<<<grid, 256, FLASH_SMEM>>>();
    }
    {
        combine_kernel<<<(N_TOK * DIM / 4) / 256, 256>>>();
    }
    {
        dim3 grid(DIM / 128, N_TOK / 64);
        proj_mma_kernel<<<grid, 256>>>(w_proj, b_proj, out);
    }
}

// round 13
// speedup vs baseline: 1.6971x; 1.6971x over previous
#include <cuda_runtime.h>
#include <cuda_bf16.h>
#include <math.h>
#include <stdint.h>

#define N_TOK 4096
#define DIM   768
#define NH    12
#define HD    64
#define SCALE 0.125f   // 1/sqrt(64)
#define LOG2E 1.44269504088896340736f
#define NSPLIT 4
#define TILES_PER_SPLIT (N_TOK / 64 / NSPLIT)   // 16

// Scratch (allocation-free rule: device globals)
// g_q holds tf32 bits of q*SCALE*LOG2E; g_k/g_v hold tf32 bits of k/v.
__device__ float g_q[NH * N_TOK * HD];
__device__ float g_k[NH * N_TOK * HD];
__device__ float g_v[NH * N_TOK * HD];
__device__ float g_att[N_TOK * DIM];
__device__ float g_po[NSPLIT * N_TOK * DIM];        // partial O per split
__device__ float g_pl[NSPLIT * NH * N_TOK];         // partial row sums

// ---------------------------------------------------------------------------
// helpers
// ---------------------------------------------------------------------------
__device__ __forceinline__ uint32_t f2tf(float f) {
    uint32_t r;
    asm("cvt.rna.tf32.f32 %0, %1;" : "=r"(r) : "f"(f));
    return r;
}

__device__ __forceinline__ float ex2(float x) {
    float r;
    asm("ex2.approx.f32 %0, %1;" : "=f"(r) : "f"(x));
    return r;
}

__device__ __forceinline__ void mma_tf32(float& c0, float& c1, float& c2, float& c3,
                                         uint32_t a0, uint32_t a1, uint32_t a2, uint32_t a3,
                                         uint32_t b0, uint32_t b1) {
    asm volatile("mma.sync.aligned.m16n8k8.row.col.f32.tf32.tf32.f32 "
                 "{%0,%1,%2,%3}, {%4,%5,%6,%7}, {%8,%9}, {%0,%1,%2,%3};"
                 : "+f"(c0), "+f"(c1), "+f"(c2), "+f"(c3)
                 : "r"(a0), "r"(a1), "r"(a2), "r"(a3), "r"(b0), "r"(b1));
}

__device__ __forceinline__ uint32_t cvta_smem(const void* p) {
    uint32_t a;
    asm("{ .reg .u64 t; cvta.to.shared.u64 t, %1; cvt.u32.u64 %0, t; }"
        : "=r"(a) : "l"(p));
    return a;
}

#define CP_ASYNC16(dst, src) \
    asm volatile("cp.async.cg.shared.global [%0], [%1], 16;" :: "r"(dst), "l"(src))
#define CP_COMMIT() asm volatile("cp.async.commit_group;" ::: "memory")
#define CP_WAIT0()  asm volatile("cp.async.wait_group 0;" ::: "memory")

// Write tf32 bits at scatter time. Q additionally pre-scaled by SCALE*LOG2E so
// flash's softmax is a bare ex2.approx. Numerically: p = 2^(s*log2e) = exp(s).
__device__ __forceinline__ void qkv_scatter(int m, int c, float v) {
    int s = c / DIM;
    int rem = c - s * DIM;
    int h = rem >> 6;
    int d = rem & 63;
    float* dst = (s == 0) ? g_q : (s == 1) ? g_k : g_v;
    float val = (s == 0) ? v * (SCALE * LOG2E) : v;
    dst[((size_t)h * N_TOK + m) * HD + d] = __uint_as_float(f2tf(val));
}

// ---------------------------------------------------------------------------
// Kernel 1: qkv = x @ w_qkv^T  (tf32 mma.sync), scatter into head-major Q/K/V
// R10-proven version: 256 threads, warp grid 2x4, warp tile 64x32.
// ---------------------------------------------------------------------------
__global__ __launch_bounds__(256) void qkv_mma_kernel(const float* __restrict__ A,
                                                      const float* __restrict__ W) {
    __shared__ uint32_t sA[128 * 36];
    __shared__ uint32_t sB[128 * 36];
    const int bm = blockIdx.y * 128;
    const int bn = blockIdx.x * 128;
    const int tid = threadIdx.x;
    const int wid = tid >> 5;
    const int lane = tid & 31;
    const int gid = lane >> 2;
    const int tig = lane & 3;
    const int wm = wid >> 2;
    const int wn = wid & 3;

    float acc[4][4][4];
#pragma unroll
    for (int mi = 0; mi < 4; mi++)
#pragma unroll
        for (int ni = 0; ni < 4; ni++)
#pragma unroll
            for (int t = 0; t < 4; t++) acc[mi][ni][t] = 0.f;

    const int lr = tid >> 3;
    const int lc = (tid & 7) << 2;

    for (int k0 = 0; k0 < DIM; k0 += 32) {
        float4 av[4], bv[4];
#pragma unroll
        for (int i = 0; i < 4; i++) {
            int r = lr + i * 32;
            av[i] = *(const float4*)(A + (size_t)(bm + r) * DIM + k0 + lc);
            bv[i] = *(const float4*)(W + (size_t)(bn + r) * DIM + k0 + lc);
        }
        __syncthreads();
#pragma unroll
        for (int i = 0; i < 4; i++) {
            int r = lr + i * 32;
            *(uint4*)(sA + r * 36 + lc) =
                make_uint4(f2tf(av[i].x), f2tf(av[i].y), f2tf(av[i].z), f2tf(av[i].w));
            *(uint4*)(sB + r * 36 + lc) =
                make_uint4(f2tf(bv[i].x), f2tf(bv[i].y), f2tf(bv[i].z), f2tf(bv[i].w));
        }
        __syncthreads();

#pragma unroll
        for (int ks = 0; ks < 4; ks++) {
            const int kk = ks * 8;
            uint32_t af[4][4];
#pragma unroll
            for (int mi = 0; mi < 4; mi++) {
                int row = wm * 64 + mi * 16 + gid;
                af[mi][0] = sA[row * 36 + kk + tig];
                af[mi][1] = sA[(row + 8) * 36 + kk + tig];
                af[mi][2] = sA[row * 36 + kk + tig + 4];
                af[mi][3] = sA[(row + 8) * 36 + kk + tig + 4];
            }
            uint32_t bf[4][2];
#pragma unroll
            for (int ni = 0; ni < 4; ni++) {
                int n = wn * 32 + ni * 8 + gid;
                bf[ni][0] = sB[n * 36 + kk + tig];
                bf[ni][1] = sB[n * 36 + kk + tig + 4];
            }
#pragma unroll
            for (int mi = 0; mi < 4; mi++)
#pragma unroll
                for (int ni = 0; ni < 4; ni++)
                    mma_tf32(acc[mi][ni][0], acc[mi][ni][1], acc[mi][ni][2], acc[mi][ni][3],
                             af[mi][0], af[mi][1], af[mi][2], af[mi][3],
                             bf[ni][0], bf[ni][1]);
        }
    }

#pragma unroll
    for (int mi = 0; mi < 4; mi++) {
        int r = bm + wm * 64 + mi * 16 + gid;
#pragma unroll
        for (int ni = 0; ni < 4; ni++) {
            int c = bn + wn * 32 + ni * 8 + 2 * tig;
            qkv_scatter(r, c, acc[mi][ni][0]);
            qkv_scatter(r, c + 1, acc[mi][ni][1]);
            qkv_scatter(r + 8, c, acc[mi][ni][2]);
            qkv_scatter(r + 8, c + 1, acc[mi][ni][3]);
        }
    }
}

// ---------------------------------------------------------------------------
// Kernel 2: flash attention, tf32 mma.sync, 4-way split-K, cp.async pipeline.
// grid (4096/128, 12, NSPLIT), 256 threads (8 warps), 2 CTAs/SM.
// K/V already tf32 bits in gmem -> raw 16B cp.async into double-buffered smem.
// Softmax: p = ex2(s) with log2(e) folded into Q. Partials additive.
// smem words: sK[2][64*68] | sV[2][64*72] | sP[128*68]
// ---------------------------------------------------------------------------
#define SKS 68
#define SVS 72
#define SPS 68
#define KOFF(b) ((b) * (64 * SKS))
#define VOFF(b) (2 * 64 * SKS + (b) * (64 * SVS))
#define POFF    (2 * 64 * SKS + 2 * 64 * SVS)
#define FLASH_SMEM ((2 * 64 * SKS + 2 * 64 * SVS + 128 * SPS) * 4)

__global__ __launch_bounds__(256, 2) void flash_split_kernel() {
    extern __shared__ uint32_t smem[];
    uint32_t* sP = smem + POFF;
    const uint32_t sbase = cvta_smem(smem);

    const int tid = threadIdx.x;
    const int wid = tid >> 5;
    const int lane = tid & 31;
    const int gid = lane >> 2;
    const int tig = lane & 3;
    const int h = blockIdx.y;
    const int q0 = blockIdx.x * 128;
    const int sp = blockIdx.z;

    const float* Qh = g_q + (size_t)h * N_TOK * HD;
    const float* Kh = g_k + (size_t)h * N_TOK * HD;
    const float* Vh = g_v + (size_t)h * N_TOK * HD;

    // Q fragments: already tf32 bits (pre-scaled) in gmem
    const int qrow = q0 + wid * 16 + gid;
    uint32_t qa[8][4];
#pragma unroll
    for (int kt = 0; kt < 8; kt++) {
        int c = kt * 8 + tig;
        qa[kt][0] = __float_as_uint(Qh[(size_t)qrow * HD + c]);
        qa[kt][1] = __float_as_uint(Qh[(size_t)(qrow + 8) * HD + c]);
        qa[kt][2] = __float_as_uint(Qh[(size_t)qrow * HD + c + 4]);
        qa[kt][3] = __float_as_uint(Qh[(size_t)(qrow + 8) * HD + c + 4]);
    }

    float o[8][4];
#pragma unroll
    for (int nt = 0; nt < 8; nt++)
#pragma unroll
        for (int t = 0; t < 4; t++) o[nt][t] = 0.f;
    float l0 = 0.f, l1 = 0.f;

    const int ldr = tid >> 4;          // 0..15
    const int ldc = (tid & 15) << 2;   // word col 0..60
    const int prow = wid * 16 + gid;

    const int kb_beg = sp * (TILES_PER_SPLIT * 64);

    // prologue: async-copy tile 0 into buffer 0
#pragma unroll
    for (int i = 0; i < 4; i++) {
        int r = ldr + i * 16;
        CP_ASYNC16(sbase + (KOFF(0) + r * SKS + ldc) * 4,
                   Kh + (size_t)(kb_beg + r) * HD + ldc);
        CP_ASYNC16(sbase + (VOFF(0) + r * SVS + ldc) * 4,
                   Vh + (size_t)(kb_beg + r) * HD + ldc);
    }
    CP_COMMIT();

    for (int it = 0; it < TILES_PER_SPLIT; it++) {
        const int b = it & 1;
        const uint32_t* sK = smem + KOFF(b);
        const uint32_t* sV = smem + VOFF(b);

        CP_WAIT0();          // tile it landed (had full previous compute to fly)
        __syncthreads();     // visibility + everyone done reading buf b from it-2

        // issue copies for tile it+1 into the other buffer; overlaps compute
        if (it + 1 < TILES_PER_SPLIT) {
            const int kbn = kb_beg + (it + 1) * 64;
            const int nb = (it + 1) & 1;
#pragma unroll
            for (int i = 0; i < 4; i++) {
                int r = ldr + i * 16;
                CP_ASYNC16(sbase + (KOFF(nb) + r * SKS + ldc) * 4,
                           Kh + (size_t)(kbn + r) * HD + ldc);
                CP_ASYNC16(sbase + (VOFF(nb) + r * SVS + ldc) * 4,
                           Vh + (size_t)(kbn + r) * HD + ldc);
            }
            CP_COMMIT();
        }

        // S = Q K^T : per warp 16 x 64
        float s[8][4];
#pragma unroll
        for (int nt = 0; nt < 8; nt++)
#pragma unroll
            for (int t = 0; t < 4; t++) s[nt][t] = 0.f;
#pragma unroll
        for (int kt = 0; kt < 8; kt++) {
#pragma unroll
            for (int nt = 0; nt < 8; nt++) {
                uint32_t b0 = sK[(nt * 8 + gid) * SKS + kt * 8 + tig];
                uint32_t b1 = sK[(nt * 8 + gid) * SKS + kt * 8 + tig + 4];
                mma_tf32(s[nt][0], s[nt][1], s[nt][2], s[nt][3],
                         qa[kt][0], qa[kt][1], qa[kt][2], qa[kt][3], b0, b1);
            }
        }

        // softmax: p = 2^s (log2e folded into Q), write P to smem
#pragma unroll
        for (int nt = 0; nt < 8; nt++) {
            float p0 = ex2(s[nt][0]);
            float p1 = ex2(s[nt][1]);
            float p2 = ex2(s[nt][2]);
            float p3 = ex2(s[nt][3]);
            l0 += p0 + p1;
            l1 += p2 + p3;
            int c = nt * 8 + 2 * tig;
            sP[prow * SPS + c] = f2tf(p0);
            sP[prow * SPS + c + 1] = f2tf(p1);
            sP[(prow + 8) * SPS + c] = f2tf(p2);
            sP[(prow + 8) * SPS + c + 1] = f2tf(p3);
        }
        __syncwarp();   // sP rows of this q-group are warp-local

        // O += P V
#pragma unroll
        for (int kt = 0; kt < 8; kt++) {
            uint32_t pa0 = sP[prow * SPS + kt * 8 + tig];
            uint32_t pa1 = sP[(prow + 8) * SPS + kt * 8 + tig];
            uint32_t pa2 = sP[prow * SPS + kt * 8 + tig + 4];
            uint32_t pa3 = sP[(prow + 8) * SPS + kt * 8 + tig + 4];
#pragma unroll
            for (int nt = 0; nt < 8; nt++) {
                uint32_t b0 = sV[(kt * 8 + tig) * SVS + nt * 8 + gid];
                uint32_t b1 = sV[(kt * 8 + tig + 4) * SVS + nt * 8 + gid];
                mma_tf32(o[nt][0], o[nt][1], o[nt][2], o[nt][3],
                         pa0, pa1, pa2, pa3, b0, b1);
            }
        }
    }

    // quad-reduce row sums
    l0 += __shfl_xor_sync(0xffffffffu, l0, 1);
    l0 += __shfl_xor_sync(0xffffffffu, l0, 2);
    l1 += __shfl_xor_sync(0xffffffffu, l1, 1);
    l1 += __shfl_xor_sync(0xffffffffu, l1, 2);

    // write unnormalized partials
    float* po = g_po + (size_t)sp * N_TOK * DIM;
#pragma unroll
    for (int nt = 0; nt < 8; nt++) {
        int c = h * HD + nt * 8 + 2 * tig;
        *(float2*)(po + (size_t)(q0 + prow) * DIM + c) = make_float2(o[nt][0], o[nt][1]);
        *(float2*)(po + (size_t)(q0 + prow + 8) * DIM + c) = make_float2(o[nt][2], o[nt][3]);
    }
    if (tig == 0) {
        g_pl[((size_t)sp * NH + h) * N_TOK + q0 + prow] = l0;
        g_pl[((size_t)sp * NH + h) * N_TOK + q0 + prow + 8] = l1;
    }
}

// ---------------------------------------------------------------------------
// Kernel 2b: combine split partials: g_att = sum(O_s) / sum(l_s)
// ---------------------------------------------------------------------------
__global__ __launch_bounds__(256) void combine_kernel() {
    const int idx = blockIdx.x * 256 + threadIdx.x;   // float4 index
    const int n = idx / (DIM / 4);
    const int c4 = idx - n * (DIM / 4);
    const int h = c4 >> 4;                            // (c4*4)/64

    float l = 0.f;
    float4 acc = make_float4(0.f, 0.f, 0.f, 0.f);
#pragma unroll
    for (int sp = 0; sp < NSPLIT; sp++) {
        l += g_pl[((size_t)sp * NH + h) * N_TOK + n];
        float4 v = *(const float4*)(g_po + (size_t)sp * N_TOK * DIM + (size_t)n * DIM + c4 * 4);
        acc.x += v.x; acc.y += v.y; acc.z += v.z; acc.w += v.w;
    }
    float inv = 1.f / l;
    *(float4*)(g_att + (size_t)n * DIM + c4 * 4) =
        make_float4(acc.x * inv, acc.y * inv, acc.z * inv, acc.w * inv);
}

// ---------------------------------------------------------------------------
// Kernel 3: out = att @ w_proj^T + b_proj  (tf32 mma.sync)
// BM=64, BN=128 -> grid (6, 64) = 384 CTAs, 3 CTAs/SM: single ~86% wave.
// ---------------------------------------------------------------------------
__global__ __launch_bounds__(256, 3) void proj_mma_kernel(const float* __restrict__ W,
                                                          const float* __restrict__ bias,
                                                          float* __restrict__ out) {
    __shared__ uint32_t sA[64 * 36];
    __shared__ uint32_t sB[128 * 36];
    const int bm = blockIdx.y * 64;
    const int bn = blockIdx.x * 128;
    const int tid = threadIdx.x;
    const int wid = tid >> 5;
    const int lane = tid & 31;
    const int gid = lane >> 2;
    const int tig = lane & 3;
    const int wm = wid >> 2;   // 0..1 (32 rows each)
    const int wn = wid & 3;    // 0..3 (32 cols each)
    const float* A = g_att;

    float acc[2][4][4];
#pragma unroll
    for (int mi = 0; mi < 2; mi++)
#pragma unroll
        for (int ni = 0; ni < 4; ni++)
#pragma unroll
            for (int t = 0; t < 4; t++) acc[mi][ni][t] = 0.f;

    const int lr = tid >> 3;          // 0..31
    const int lc = (tid & 7) << 2;    // 0..28

    for (int k0 = 0; k0 < DIM; k0 += 32) {
        float4 av[2], bv[4];
#pragma unroll
        for (int i = 0; i < 2; i++)
            av[i] = *(const float4*)(A + (size_t)(bm + lr + i * 32) * DIM + k0 + lc);
#pragma unroll
        for (int i = 0; i < 4; i++)
            bv[i] = *(const float4*)(W + (size_t)(bn + lr + i * 32) * DIM + k0 + lc);
        __syncthreads();
#pragma unroll
        for (int i = 0; i < 2; i++) {
            int r = lr + i * 32;
            *(uint4*)(sA + r * 36 + lc) =
                make_uint4(f2tf(av[i].x), f2tf(av[i].y), f2tf(av[i].z), f2tf(av[i].w));
        }
#pragma unroll
        for (int i = 0; i < 4; i++) {
            int r = lr + i * 32;
            *(uint4*)(sB + r * 36 + lc) =
                make_uint4(f2tf(bv[i].x), f2tf(bv[i].y), f2tf(bv[i].z), f2tf(bv[i].w));
        }
        __syncthreads();

#pragma unroll
        for (int ks = 0; ks < 4; ks++) {
            const int kk = ks * 8;
            uint32_t af[2][4];
#pragma unroll
            for (int mi = 0; mi < 2; mi++) {
                int row = wm * 32 + mi * 16 + gid;
                af[mi][0] = sA[row * 36 + kk + tig];
                af[mi][1] = sA[(row + 8) * 36 + kk + tig];
                af[mi][2] = sA[row * 36 + kk + tig + 4];
                af[mi][3] = sA[(row + 8) * 36 + kk + tig + 4];
            }
            uint32_t bf[4][2];
#pragma unroll
            for (int ni = 0; ni < 4; ni++) {
                int n = wn * 32 + ni * 8 + gid;
                bf[ni][0] = sB[n * 36 + kk + tig];
                bf[ni][1] = sB[n * 36 + kk + tig + 4];
            }
#pragma unroll
            for (int mi = 0; mi < 2; mi++)
#pragma unroll
                for (int ni = 0; ni < 4; ni++)
                    mma_tf32(acc[mi][ni][0], acc[mi][ni][1], acc[mi][ni][2], acc[mi][ni][3],
                             af[mi][0], af[mi][1], af[mi][2], af[mi][3],
                             bf[ni][0], bf[ni][1]);
        }
    }

#pragma unroll
    for (int mi = 0; mi < 2; mi++) {
        int r = bm + wm * 32 + mi * 16 + gid;
#pragma unroll
        for (int ni = 0; ni < 4; ni++) {
            int c = bn + wn * 32 + ni * 8 + 2 * tig;
            out[(size_t)r * DIM + c]           = acc[mi][ni][0] + bias[c];
            out[(size_t)r * DIM + c + 1]       = acc[mi][ni][1] + bias[c + 1];
            out[(size_t)(r + 8) * DIM + c]     = acc[mi][ni][2] + bias[c];
            out[(size_t)(r + 8) * DIM + c + 1] = acc[mi][ni][3] + bias[c + 1];
        }
    }
}

// ---------------------------------------------------------------------------
extern "C" void kernel_launch(void* const* d_in, const int* in_sizes, int n_in,
                              void* d_out, int out_size) {
    const float* x      = (const float*)d_in[0];   // [4096, 768]
    const float* w_qkv  = (const float*)d_in[1];   // [2304, 768]
    const float* w_proj = (const float*)d_in[2];   // [768, 768]
    const float* b_proj = (const float*)d_in[3];   // [768]
    float* out = (float*)d_out;                    // [4096, 768]

    static bool attr_set = false;
    if (!attr_set) {
        cudaFuncSetAttribute(flash_split_kernel,
                             cudaFuncAttributeMaxDynamicSharedMemorySize, FLASH_SMEM);
        attr_set = true;
    }

    {
        dim3 grid(2304 / 128, N_TOK / 128);
        qkv_mma_kernel<<<grid, 256>>>(x, w_qkv);
    }
    {
        dim3 grid(N_TOK / 128, NH, NSPLIT);
        flash_split_kernel<<<grid, 256, FLASH_SMEM>>>();
    }
    {
        combine_kernel<<<(N_TOK * DIM / 4) / 256, 256>>>();
    }
    {
        dim3 grid(DIM / 128, N_TOK / 64);
        proj_mma_kernel<<<grid, 256>>>(w_proj, b_proj, out);
    }
}